// round 11
// baseline (speedup 1.0000x reference)
#include <cuda_runtime.h>
#include <cuda_fp16.h>
#include <mma.h>
#include <cstdint>

using namespace nvcuda;

#define N_NODES 50000
#define N_EDGES 800000
#define F 128
#define GRM 128                 // rows per GEMM block
#define LDA 136                 // padded leading dim (halves)
#define CH 256
#define NCH ((N_NODES + CH - 1) / CH)   // 196
#define SMEM_GEMM (2 * GRM * LDA * 2)   // A + B tiles: 69632 B

// ---- scratch (no allocation allowed -> __device__ globals) ----
// deg arrays re-zeroed in k_fill_prep; g_c reset by owning gemm2 block;
// g_vec/g_done reset by gemm2's last block. Module zero-init covers run 1.
__device__ int    g_deg_src[N_NODES];
__device__ int    g_deg_dst[N_NODES];
__device__ float  g_out_norm[N_NODES];
__device__ float  g_in_norm[N_NODES];
__device__ int    g_row_ptr[N_NODES + 1];
__device__ int    g_cursor[N_NODES];
__device__ int    g_col_idx[N_EDGES];
__device__ int    g_chunk_sum[NCH];
__device__ float  g_c[N_NODES];        // c[s] = sum_{e: src=s} in_norm[dst_e]
__device__ __half g_x0[N_NODES * F];
__device__ __half g_x1[N_NODES * F];
__device__ __half g_m[N_NODES * F];
__device__ __half g_w1h[F * F];
__device__ __half g_w2h[F * F];
__device__ float  g_vec[F];
__device__ int    g_done;

// ---------------- setup ----------------
// degrees (4 edges/thread, int4) + W1/W2 -> fp16
__global__ void k_count(const int4* __restrict__ src4, const int4* __restrict__ dst4,
                        const float* __restrict__ W1, const float* __restrict__ W2) {
    int i = blockIdx.x * blockDim.x + threadIdx.x;
    if (i < N_EDGES / 4) {
        int4 s = src4[i], d = dst4[i];
        atomicAdd(&g_deg_src[s.x], 1);
        atomicAdd(&g_deg_src[s.y], 1);
        atomicAdd(&g_deg_src[s.z], 1);
        atomicAdd(&g_deg_src[s.w], 1);
        atomicAdd(&g_deg_dst[d.x], 1);
        atomicAdd(&g_deg_dst[d.y], 1);
        atomicAdd(&g_deg_dst[d.z], 1);
        atomicAdd(&g_deg_dst[d.w], 1);
    }
    if (i < F * F) {
        g_w1h[i] = __float2half(W1[i]);
        g_w2h[i] = __float2half(W2[i]);
    }
}

__global__ void k_scan1() {
    __shared__ int s[CH];
    int t = threadIdx.x;
    int i = blockIdx.x * CH + t;
    int v = (i < N_NODES) ? g_deg_dst[i] : 0;
    s[t] = v;
    __syncthreads();
    for (int off = 1; off < CH; off <<= 1) {
        int x = 0;
        if (t >= off) x = s[t - off];
        __syncthreads();
        if (t >= off) s[t] += x;
        __syncthreads();
    }
    if (i < N_NODES) g_row_ptr[i + 1] = s[t];
    if (t == CH - 1) g_chunk_sum[blockIdx.x] = s[t];
}

// finalize: each block re-scans chunk sums locally; rsqrt spread over SMs
__global__ void k_scan23() {
    __shared__ int s[CH];
    int t = threadIdx.x;
    int bid = blockIdx.x;
    int v = (t < NCH) ? g_chunk_sum[t] : 0;
    s[t] = v;
    __syncthreads();
    for (int off = 1; off < CH; off <<= 1) {
        int x = 0;
        if (t >= off) x = s[t - off];
        __syncthreads();
        if (t >= off) s[t] += x;
        __syncthreads();
    }
    int chunk_off = (bid > 0) ? s[bid - 1] : 0;
    int i = bid * CH + t;
    if (i < N_NODES) {
        int rp = g_row_ptr[i + 1] + chunk_off;
        g_row_ptr[i + 1] = rp;
        int d = g_deg_dst[i];
        g_cursor[i] = rp - d;
        g_in_norm[i]  = rsqrtf((float)max(d, 1));
        g_out_norm[i] = rsqrtf((float)max(g_deg_src[i], 1));
        if (i == 0) g_row_ptr[0] = 0;
    }
}

// CSR fill (int4) + c[s] accumulation + feat -> fp16 prescale + deg re-zero
__global__ void k_fill_prep(const int4* __restrict__ src4, const int4* __restrict__ dst4,
                            const float* __restrict__ feat) {
    int i = blockIdx.x * blockDim.x + threadIdx.x;
    if (i < N_NODES) { g_deg_src[i] = 0; g_deg_dst[i] = 0; }   // reset for next replay
    if (i < N_EDGES / 4) {
        int4 s = src4[i], d = dst4[i];
        float i0 = g_in_norm[d.x], i1 = g_in_norm[d.y];
        float i2 = g_in_norm[d.z], i3 = g_in_norm[d.w];
        int p;
        p = atomicAdd(&g_cursor[d.x], 1); g_col_idx[p] = s.x;
        p = atomicAdd(&g_cursor[d.y], 1); g_col_idx[p] = s.y;
        p = atomicAdd(&g_cursor[d.z], 1); g_col_idx[p] = s.z;
        p = atomicAdd(&g_cursor[d.w], 1); g_col_idx[p] = s.w;
        atomicAdd(&g_c[s.x], i0);
        atomicAdd(&g_c[s.y], i1);
        atomicAdd(&g_c[s.z], i2);
        atomicAdd(&g_c[s.w], i3);
    }
    if (i < N_NODES * F / 4) {
        int base = i * 4;
        float on = g_out_norm[base >> 7];
        float4 v = *(const float4*)&feat[base];
        __half2 h01 = __floats2half2_rn(v.x * on, v.y * on);
        __half2 h23 = __floats2half2_rn(v.z * on, v.w * on);
        uint2 pk;
        pk.x = *(uint32_t*)&h01;
        pk.y = *(uint32_t*)&h23;
        *(uint2*)&g_x0[base] = pk;
    }
}

// ---------------- gather: warp per node, unroll 8, 2-level fp16 tree ----------------
__global__ void __launch_bounds__(256)
k_agg(const __half* __restrict__ x, __half* __restrict__ m) {
    int w = (blockIdx.x * blockDim.x + threadIdx.x) >> 5;
    int lane = threadIdx.x & 31;
    if (w >= N_NODES) return;
    const uint2* x2 = (const uint2*)x;
    const int* __restrict__ ci = g_col_idx;
    int beg = g_row_ptr[w], end = g_row_ptr[w + 1];
    float4 a0 = {0.f, 0.f, 0.f, 0.f};
    float4 a1 = {0.f, 0.f, 0.f, 0.f};
    int e = beg;
    for (; e + 8 <= end; e += 8) {
        uint2 v[8];
#pragma unroll
        for (int j = 0; j < 8; j++) v[j] = x2[ci[e + j] * 32 + lane];
        __half2 c0x = __hadd2(*(__half2*)&v[0].x, *(__half2*)&v[1].x);
        __half2 c0y = __hadd2(*(__half2*)&v[0].y, *(__half2*)&v[1].y);
        __half2 c1x = __hadd2(*(__half2*)&v[2].x, *(__half2*)&v[3].x);
        __half2 c1y = __hadd2(*(__half2*)&v[2].y, *(__half2*)&v[3].y);
        __half2 c2x = __hadd2(*(__half2*)&v[4].x, *(__half2*)&v[5].x);
        __half2 c2y = __hadd2(*(__half2*)&v[4].y, *(__half2*)&v[5].y);
        __half2 c3x = __hadd2(*(__half2*)&v[6].x, *(__half2*)&v[7].x);
        __half2 c3y = __hadd2(*(__half2*)&v[6].y, *(__half2*)&v[7].y);
        __half2 q0x = __hadd2(c0x, c1x);
        __half2 q0y = __hadd2(c0y, c1y);
        __half2 q1x = __hadd2(c2x, c3x);
        __half2 q1y = __hadd2(c2y, c3y);
        float2 f0x = __half22float2(q0x), f0y = __half22float2(q0y);
        float2 f1x = __half22float2(q1x), f1y = __half22float2(q1y);
        a0.x += f0x.x; a0.y += f0x.y; a0.z += f0y.x; a0.w += f0y.y;
        a1.x += f1x.x; a1.y += f1x.y; a1.z += f1y.x; a1.w += f1y.y;
    }
    for (; e < end; e++) {
        uint2 v = x2[ci[e] * 32 + lane];
        float2 pa = __half22float2(*(__half2*)&v.x);
        float2 pb = __half22float2(*(__half2*)&v.y);
        a0.x += pa.x; a0.y += pa.y; a0.z += pb.x; a0.w += pb.y;
    }
    float sc = g_in_norm[w];
    __half2 h01 = __floats2half2_rn((a0.x + a1.x) * sc, (a0.y + a1.y) * sc);
    __half2 h23 = __floats2half2_rn((a0.z + a1.z) * sc, (a0.w + a1.w) * sc);
    uint2 pk;
    pk.x = *(uint32_t*)&h01;
    pk.y = *(uint32_t*)&h23;
    ((uint2*)m)[w * 32 + lane] = pk;
}

// ---------------- GEMM: m @ W + b -> relu -> *out_norm ----------------
// FOLD=false: write fp16 activations to y.
// FOLD=true:  multiply rows by c[row], reduce into g_vec; last block does
//             out = g_vec @ W3 + b3 (y not written).
template<bool FOLD>
__global__ void __launch_bounds__(256, 2)
k_gemm(const __half* __restrict__ m, const __half* __restrict__ wh,
       const float* __restrict__ b, __half* __restrict__ y,
       const float* __restrict__ W3, const float* __restrict__ b3,
       float* __restrict__ out) {
    extern __shared__ char smem[];
    __half* sA = (__half*)smem;                        // [128][LDA]
    __half* sB = (__half*)(smem + GRM * LDA * 2);      // [128][LDA]
    float*  scc = (float*)smem + 4096;                 // col accumulator (FOLD)
    int t = threadIdx.x, warp = t >> 5, lane = t & 31;
    int row0 = blockIdx.x * GRM;

    {
        const uint4* asrc = (const uint4*)(m + (size_t)row0 * F);
        const uint4* bsrc = (const uint4*)wh;
        for (int i = t; i < GRM * 16; i += 256) {
            int r = i >> 4, c = i & 15;
            uint4 av = {0u, 0u, 0u, 0u};
            if (row0 + r < N_NODES) av = asrc[i];
            *(uint4*)&sA[r * LDA + c * 8] = av;
            *(uint4*)&sB[r * LDA + c * 8] = bsrc[i];
        }
    }
    __syncthreads();

    int wy = warp >> 1, wx = warp & 1;
    wmma::fragment<wmma::accumulator, 16, 16, 16, float> c[2][4];
#pragma unroll
    for (int i = 0; i < 2; i++)
#pragma unroll
        for (int j = 0; j < 4; j++) wmma::fill_fragment(c[i][j], 0.f);

#pragma unroll
    for (int k0 = 0; k0 < F; k0 += 16) {
        wmma::fragment<wmma::matrix_a, 16, 16, 16, __half, wmma::row_major> af[2];
        wmma::fragment<wmma::matrix_b, 16, 16, 16, __half, wmma::row_major> bf[4];
#pragma unroll
        for (int i = 0; i < 2; i++)
            wmma::load_matrix_sync(af[i], &sA[(wy * 32 + i * 16) * LDA + k0], LDA);
#pragma unroll
        for (int j = 0; j < 4; j++)
            wmma::load_matrix_sync(bf[j], &sB[k0 * LDA + wx * 64 + j * 16], LDA);
#pragma unroll
        for (int i = 0; i < 2; i++)
#pragma unroll
            for (int j = 0; j < 4; j++)
                wmma::mma_sync(c[i][j], af[i], bf[j], c[i][j]);
    }
    __syncthreads();

    if (FOLD) {
        if (t < F) scc[t] = 0.f;
        __syncthreads();
    }

    float* wscr = (float*)smem + warp * (16 * 20);
#pragma unroll
    for (int i = 0; i < 2; i++) {
#pragma unroll
        for (int j = 0; j < 4; j++) {
            wmma::store_matrix_sync(wscr, c[i][j], 20, wmma::mem_row_major);
            __syncwarp();
            if (lane < 16) {
                int grow = row0 + wy * 32 + i * 16 + lane;
                if (grow < N_NODES) {
                    float on = g_out_norm[grow];
                    const float* cr = &wscr[lane * 20];
                    if (FOLD) {
                        float cv = g_c[grow] * on;
#pragma unroll
                        for (int cc = 0; cc < 16; cc += 4) {
                            float4 bv = *(const float4*)&b[wx * 64 + j * 16 + cc];
                            atomicAdd(&scc[wx * 64 + j * 16 + cc],     fmaxf(cr[cc]     + bv.x, 0.f) * cv);
                            atomicAdd(&scc[wx * 64 + j * 16 + cc + 1], fmaxf(cr[cc + 1] + bv.y, 0.f) * cv);
                            atomicAdd(&scc[wx * 64 + j * 16 + cc + 2], fmaxf(cr[cc + 2] + bv.z, 0.f) * cv);
                            atomicAdd(&scc[wx * 64 + j * 16 + cc + 3], fmaxf(cr[cc + 3] + bv.w, 0.f) * cv);
                        }
                    } else {
                        __half2 hv[8];
#pragma unroll
                        for (int cc = 0; cc < 16; cc += 4) {
                            float4 bv = *(const float4*)&b[wx * 64 + j * 16 + cc];
                            float v0 = fmaxf(cr[cc]     + bv.x, 0.f) * on;
                            float v1 = fmaxf(cr[cc + 1] + bv.y, 0.f) * on;
                            float v2 = fmaxf(cr[cc + 2] + bv.z, 0.f) * on;
                            float v3 = fmaxf(cr[cc + 3] + bv.w, 0.f) * on;
                            hv[cc / 2]     = __floats2half2_rn(v0, v1);
                            hv[cc / 2 + 1] = __floats2half2_rn(v2, v3);
                        }
                        uint4* dstp = (uint4*)(y + (size_t)grow * F + wx * 64 + j * 16);
                        dstp[0] = *(uint4*)&hv[0];
                        dstp[1] = *(uint4*)&hv[4];
                    }
                }
            }
            __syncwarp();
        }
    }

    if (FOLD) {
        __syncthreads();
        if (t < F) atomicAdd(&g_vec[t], scc[t] * (1.0f / N_NODES));
        // reset c for this block's rows (only this block reads them)
        {
            int grow = row0 + t;
            if (t < GRM && grow < N_NODES) g_c[grow] = 0.f;
        }
        if (t + 128 < GRM) { } // GRM==128: covered above
        __threadfence();
        __syncthreads();
        __shared__ int s_last;
        if (t == 0) s_last = (atomicAdd(&g_done, 1) == (int)gridDim.x - 1);
        __syncthreads();
        if (s_last) {
            __shared__ float sv[F];
            if (t < F) sv[t] = *((volatile float*)&g_vec[t]);
            __syncthreads();
            if (t < F) {
                float acc = b3[t];
#pragma unroll 8
                for (int k = 0; k < F; k++) acc += sv[k] * W3[k * F + t];
                out[t] = acc;
                g_vec[t] = 0.f;
            }
            if (t == 0) g_done = 0;
        }
    }
}

extern "C" void kernel_launch(void* const* d_in, const int* in_sizes, int n_in,
                              void* d_out, int out_size) {
    const float* feat = (const float*)d_in[0];
    const float* W1   = (const float*)d_in[1];
    const float* b1   = (const float*)d_in[2];
    const float* W2   = (const float*)d_in[3];
    const float* b2   = (const float*)d_in[4];
    const float* W3   = (const float*)d_in[5];
    const float* b3   = (const float*)d_in[6];
    const int*   src  = (const int*)d_in[7];
    const int*   dst  = (const int*)d_in[8];
    float* out = (float*)d_out;

    cudaFuncSetAttribute(k_gemm<false>, cudaFuncAttributeMaxDynamicSharedMemorySize, SMEM_GEMM);
    cudaFuncSetAttribute(k_gemm<true>,  cudaFuncAttributeMaxDynamicSharedMemorySize, SMEM_GEMM);

    void *p0, *p1, *pm, *pw1, *pw2;
    cudaGetSymbolAddress(&p0, g_x0);
    cudaGetSymbolAddress(&p1, g_x1);
    cudaGetSymbolAddress(&pm, g_m);
    cudaGetSymbolAddress(&pw1, g_w1h);
    cudaGetSymbolAddress(&pw2, g_w2h);
    __half* x0 = (__half*)p0;
    __half* x1 = (__half*)p1;
    __half* mm = (__half*)pm;
    __half* w1h = (__half*)pw1;
    __half* w2h = (__half*)pw2;

    int nb_count = (N_EDGES / 4 + 255) / 256;        // 782
    int nb_aggw  = (N_NODES * 32 + 255) / 256;       // 6250
    int nb_gemm  = (N_NODES + GRM - 1) / GRM;        // 391
    int nb_fp    = (N_NODES * F / 4 + 255) / 256;    // 6250

    k_count<<<nb_count, 256>>>((const int4*)src, (const int4*)dst, W1, W2);
    k_scan1<<<NCH, CH>>>();
    k_scan23<<<NCH, CH>>>();
    k_fill_prep<<<nb_fp, 256>>>((const int4*)src, (const int4*)dst, feat);   // profiled (#4)
    k_agg<<<nb_aggw, 256>>>(x0, mm);
    k_gemm<false><<<nb_gemm, 256, SMEM_GEMM>>>(mm, w1h, b1, x1, W3, b3, out);
    k_agg<<<nb_aggw, 256>>>(x1, mm);
    k_gemm<true><<<nb_gemm, 256, SMEM_GEMM>>>(mm, w2h, b2, nullptr, W3, b3, out);
}

// round 12
// speedup vs baseline: 2.4667x; 2.4667x over previous
#include <cuda_runtime.h>
#include <cuda_fp16.h>
#include <mma.h>
#include <cstdint>

using namespace nvcuda;

#define N_NODES 50000
#define N_EDGES 800000
#define F 128
#define GRM 128                 // rows per GEMM block
#define LDA 136                 // padded leading dim (halves)
#define CH 256
#define NCH ((N_NODES + CH - 1) / CH)   // 196
#define SMEM_GEMM (2 * GRM * LDA * 2)   // A + B tiles: 69632 B

// ---- scratch (no allocation allowed -> __device__ globals) ----
// deg arrays re-zeroed in k_fill_prep; g_c reset by owning gemm2 block;
// g_vec/g_done reset by gemm2's last block. Module zero-init covers run 1.
__device__ int    g_deg_src[N_NODES];
__device__ int    g_deg_dst[N_NODES];
__device__ float  g_out_norm[N_NODES];
__device__ float  g_in_norm[N_NODES];
__device__ int    g_row_ptr[N_NODES + 1];
__device__ int    g_cursor[N_NODES];
__device__ int    g_col_idx[N_EDGES];
__device__ int    g_chunk_sum[NCH];
__device__ float  g_c[N_NODES];        // c[s] = sum_{e: src=s} in_norm[dst_e]
__device__ __half g_x0[N_NODES * F];
__device__ __half g_x1[N_NODES * F];
__device__ __half g_m[N_NODES * F];
__device__ __half g_w1h[F * F];
__device__ __half g_w2h[F * F];
__device__ float  g_vec[F];
__device__ int    g_done;

// ---------------- setup ----------------
__global__ void k_count(const int4* __restrict__ src4, const int4* __restrict__ dst4,
                        const float* __restrict__ W1, const float* __restrict__ W2) {
    int i = blockIdx.x * blockDim.x + threadIdx.x;
    if (i < N_EDGES / 4) {
        int4 s = src4[i], d = dst4[i];
        atomicAdd(&g_deg_src[s.x], 1);
        atomicAdd(&g_deg_src[s.y], 1);
        atomicAdd(&g_deg_src[s.z], 1);
        atomicAdd(&g_deg_src[s.w], 1);
        atomicAdd(&g_deg_dst[d.x], 1);
        atomicAdd(&g_deg_dst[d.y], 1);
        atomicAdd(&g_deg_dst[d.z], 1);
        atomicAdd(&g_deg_dst[d.w], 1);
    }
    if (i < F * F) {
        g_w1h[i] = __float2half(W1[i]);
        g_w2h[i] = __float2half(W2[i]);
    }
}

__global__ void k_scan1() {
    __shared__ int s[CH];
    int t = threadIdx.x;
    int i = blockIdx.x * CH + t;
    int v = (i < N_NODES) ? g_deg_dst[i] : 0;
    s[t] = v;
    __syncthreads();
    for (int off = 1; off < CH; off <<= 1) {
        int x = 0;
        if (t >= off) x = s[t - off];
        __syncthreads();
        if (t >= off) s[t] += x;
        __syncthreads();
    }
    if (i < N_NODES) g_row_ptr[i + 1] = s[t];
    if (t == CH - 1) g_chunk_sum[blockIdx.x] = s[t];
}

__global__ void k_scan23() {
    __shared__ int s[CH];
    int t = threadIdx.x;
    int bid = blockIdx.x;
    int v = (t < NCH) ? g_chunk_sum[t] : 0;
    s[t] = v;
    __syncthreads();
    for (int off = 1; off < CH; off <<= 1) {
        int x = 0;
        if (t >= off) x = s[t - off];
        __syncthreads();
        if (t >= off) s[t] += x;
        __syncthreads();
    }
    int chunk_off = (bid > 0) ? s[bid - 1] : 0;
    int i = bid * CH + t;
    if (i < N_NODES) {
        int rp = g_row_ptr[i + 1] + chunk_off;
        g_row_ptr[i + 1] = rp;
        int d = g_deg_dst[i];
        g_cursor[i] = rp - d;
        g_in_norm[i]  = rsqrtf((float)max(d, 1));
        g_out_norm[i] = rsqrtf((float)max(g_deg_src[i], 1));
        if (i == 0) g_row_ptr[0] = 0;
    }
}

// CSR fill (int4) + c[s] accumulation + feat -> fp16 prescale + deg re-zero
__global__ void k_fill_prep(const int4* __restrict__ src4, const int4* __restrict__ dst4,
                            const float* __restrict__ feat) {
    int i = blockIdx.x * blockDim.x + threadIdx.x;
    if (i < N_NODES) { g_deg_src[i] = 0; g_deg_dst[i] = 0; }
    if (i < N_EDGES / 4) {
        int4 s = src4[i], d = dst4[i];
        float i0 = g_in_norm[d.x], i1 = g_in_norm[d.y];
        float i2 = g_in_norm[d.z], i3 = g_in_norm[d.w];
        int p;
        p = atomicAdd(&g_cursor[d.x], 1); g_col_idx[p] = s.x;
        p = atomicAdd(&g_cursor[d.y], 1); g_col_idx[p] = s.y;
        p = atomicAdd(&g_cursor[d.z], 1); g_col_idx[p] = s.z;
        p = atomicAdd(&g_cursor[d.w], 1); g_col_idx[p] = s.w;
        atomicAdd(&g_c[s.x], i0);
        atomicAdd(&g_c[s.y], i1);
        atomicAdd(&g_c[s.z], i2);
        atomicAdd(&g_c[s.w], i3);
    }
    if (i < N_NODES * F / 4) {
        int base = i * 4;
        float on = g_out_norm[base >> 7];
        float4 v = *(const float4*)&feat[base];
        __half2 h01 = __floats2half2_rn(v.x * on, v.y * on);
        __half2 h23 = __floats2half2_rn(v.z * on, v.w * on);
        uint2 pk;
        pk.x = *(uint32_t*)&h01;
        pk.y = *(uint32_t*)&h23;
        *(uint2*)&g_x0[base] = pk;
    }
}

// ---------------- gather: warp per node, unroll 8, 2-level fp16 tree ----------------
__global__ void __launch_bounds__(256)
k_agg(const __half* __restrict__ x, __half* __restrict__ m) {
    int w = (blockIdx.x * blockDim.x + threadIdx.x) >> 5;
    int lane = threadIdx.x & 31;
    if (w >= N_NODES) return;
    const uint2* x2 = (const uint2*)x;
    const int* __restrict__ ci = g_col_idx;
    int beg = g_row_ptr[w], end = g_row_ptr[w + 1];
    float4 a0 = {0.f, 0.f, 0.f, 0.f};
    float4 a1 = {0.f, 0.f, 0.f, 0.f};
    int e = beg;
    for (; e + 8 <= end; e += 8) {
        uint2 v[8];
#pragma unroll
        for (int j = 0; j < 8; j++) v[j] = x2[ci[e + j] * 32 + lane];
        __half2 c0x = __hadd2(*(__half2*)&v[0].x, *(__half2*)&v[1].x);
        __half2 c0y = __hadd2(*(__half2*)&v[0].y, *(__half2*)&v[1].y);
        __half2 c1x = __hadd2(*(__half2*)&v[2].x, *(__half2*)&v[3].x);
        __half2 c1y = __hadd2(*(__half2*)&v[2].y, *(__half2*)&v[3].y);
        __half2 c2x = __hadd2(*(__half2*)&v[4].x, *(__half2*)&v[5].x);
        __half2 c2y = __hadd2(*(__half2*)&v[4].y, *(__half2*)&v[5].y);
        __half2 c3x = __hadd2(*(__half2*)&v[6].x, *(__half2*)&v[7].x);
        __half2 c3y = __hadd2(*(__half2*)&v[6].y, *(__half2*)&v[7].y);
        __half2 q0x = __hadd2(c0x, c1x);
        __half2 q0y = __hadd2(c0y, c1y);
        __half2 q1x = __hadd2(c2x, c3x);
        __half2 q1y = __hadd2(c2y, c3y);
        float2 f0x = __half22float2(q0x), f0y = __half22float2(q0y);
        float2 f1x = __half22float2(q1x), f1y = __half22float2(q1y);
        a0.x += f0x.x; a0.y += f0x.y; a0.z += f0y.x; a0.w += f0y.y;
        a1.x += f1x.x; a1.y += f1x.y; a1.z += f1y.x; a1.w += f1y.y;
    }
    for (; e < end; e++) {
        uint2 v = x2[ci[e] * 32 + lane];
        float2 pa = __half22float2(*(__half2*)&v.x);
        float2 pb = __half22float2(*(__half2*)&v.y);
        a0.x += pa.x; a0.y += pa.y; a0.z += pb.x; a0.w += pb.y;
    }
    float sc = g_in_norm[w];
    __half2 h01 = __floats2half2_rn((a0.x + a1.x) * sc, (a0.y + a1.y) * sc);
    __half2 h23 = __floats2half2_rn((a0.z + a1.z) * sc, (a0.w + a1.w) * sc);
    uint2 pk;
    pk.x = *(uint32_t*)&h01;
    pk.y = *(uint32_t*)&h23;
    ((uint2*)m)[w * 32 + lane] = pk;
}

// ---------------- GEMM: m @ W + b -> relu -> *out_norm ----------------
// FOLD=false: write fp16 activations to y.
// FOLD=true:  weight rows by c[row]*out_norm, shuffle-reduce columns,
//             accumulate to g_vec; last block does out = g_vec @ W3 + b3.
template<bool FOLD>
__global__ void __launch_bounds__(256, 2)
k_gemm(const __half* __restrict__ m, const __half* __restrict__ wh,
       const float* __restrict__ b, __half* __restrict__ y,
       const float* __restrict__ W3, const float* __restrict__ b3,
       float* __restrict__ out) {
    extern __shared__ char smem[];
    __half* sA = (__half*)smem;                        // [128][LDA]
    __half* sB = (__half*)(smem + GRM * LDA * 2);      // [128][LDA]
    float*  scc = (float*)smem + 3072;                 // col accumulator (FOLD), 12288B off
    int t = threadIdx.x, warp = t >> 5, lane = t & 31;
    int row0 = blockIdx.x * GRM;

    {
        const uint4* asrc = (const uint4*)(m + (size_t)row0 * F);
        const uint4* bsrc = (const uint4*)wh;
        for (int i = t; i < GRM * 16; i += 256) {
            int r = i >> 4, c = i & 15;
            uint4 av = {0u, 0u, 0u, 0u};
            if (row0 + r < N_NODES) av = asrc[i];
            *(uint4*)&sA[r * LDA + c * 8] = av;
            *(uint4*)&sB[r * LDA + c * 8] = bsrc[i];
        }
    }
    __syncthreads();

    int wy = warp >> 1, wx = warp & 1;
    wmma::fragment<wmma::accumulator, 16, 16, 16, float> c[2][4];
#pragma unroll
    for (int i = 0; i < 2; i++)
#pragma unroll
        for (int j = 0; j < 4; j++) wmma::fill_fragment(c[i][j], 0.f);

#pragma unroll
    for (int k0 = 0; k0 < F; k0 += 16) {
        wmma::fragment<wmma::matrix_a, 16, 16, 16, __half, wmma::row_major> af[2];
        wmma::fragment<wmma::matrix_b, 16, 16, 16, __half, wmma::row_major> bf[4];
#pragma unroll
        for (int i = 0; i < 2; i++)
            wmma::load_matrix_sync(af[i], &sA[(wy * 32 + i * 16) * LDA + k0], LDA);
#pragma unroll
        for (int j = 0; j < 4; j++)
            wmma::load_matrix_sync(bf[j], &sB[k0 * LDA + wx * 64 + j * 16], LDA);
#pragma unroll
        for (int i = 0; i < 2; i++)
#pragma unroll
            for (int j = 0; j < 4; j++)
                wmma::mma_sync(c[i][j], af[i], bf[j], c[i][j]);
    }
    __syncthreads();

    if (FOLD) {
        if (t < F) scc[t] = 0.f;
        __syncthreads();
    }

    float* wscr = (float*)smem + warp * (16 * 20);
#pragma unroll
    for (int i = 0; i < 2; i++) {
#pragma unroll
        for (int j = 0; j < 4; j++) {
            wmma::store_matrix_sync(wscr, c[i][j], 20, wmma::mem_row_major);
            __syncwarp();
            if (FOLD) {
                if (lane < 16) {
                    int grow = row0 + wy * 32 + i * 16 + lane;
                    bool valid = grow < N_NODES;
                    float cv = valid ? g_c[grow] * g_out_norm[grow] : 0.f;
                    const float* cr = &wscr[lane * 20];
                    float val[16];
#pragma unroll
                    for (int cc = 0; cc < 16; cc++) {
                        float bv = b[wx * 64 + j * 16 + cc];
                        val[cc] = valid ? fmaxf(cr[cc] + bv, 0.f) * cv : 0.f;
                    }
                    // butterfly reduce across the 16 row-lanes
#pragma unroll
                    for (int off = 8; off >= 1; off >>= 1)
#pragma unroll
                        for (int cc = 0; cc < 16; cc++)
                            val[cc] += __shfl_xor_sync(0x0000FFFFu, val[cc], off, 16);
                    if (lane == 0) {
#pragma unroll
                        for (int cc = 0; cc < 16; cc++)
                            atomicAdd(&scc[wx * 64 + j * 16 + cc], val[cc]);
                    }
                }
            } else {
                if (lane < 16) {
                    int grow = row0 + wy * 32 + i * 16 + lane;
                    if (grow < N_NODES) {
                        float on = g_out_norm[grow];
                        const float* cr = &wscr[lane * 20];
                        __half2 hv[8];
#pragma unroll
                        for (int cc = 0; cc < 16; cc += 4) {
                            float4 bv = *(const float4*)&b[wx * 64 + j * 16 + cc];
                            float v0 = fmaxf(cr[cc]     + bv.x, 0.f) * on;
                            float v1 = fmaxf(cr[cc + 1] + bv.y, 0.f) * on;
                            float v2 = fmaxf(cr[cc + 2] + bv.z, 0.f) * on;
                            float v3 = fmaxf(cr[cc + 3] + bv.w, 0.f) * on;
                            hv[cc / 2]     = __floats2half2_rn(v0, v1);
                            hv[cc / 2 + 1] = __floats2half2_rn(v2, v3);
                        }
                        uint4* dstp = (uint4*)(y + (size_t)grow * F + wx * 64 + j * 16);
                        dstp[0] = *(uint4*)&hv[0];
                        dstp[1] = *(uint4*)&hv[4];
                    }
                }
            }
            __syncwarp();
        }
    }

    if (FOLD) {
        __syncthreads();
        if (t < F) atomicAdd(&g_vec[t], scc[t] * (1.0f / N_NODES));
        {
            int grow = row0 + t;
            if (t < GRM && grow < N_NODES) g_c[grow] = 0.f;   // reset for next replay
        }
        __threadfence();
        __syncthreads();
        __shared__ int s_last;
        if (t == 0) s_last = (atomicAdd(&g_done, 1) == (int)gridDim.x - 1);
        __syncthreads();
        if (s_last) {
            __shared__ float sv[F];
            if (t < F) sv[t] = *((volatile float*)&g_vec[t]);
            __syncthreads();
            if (t < F) {
                float acc = b3[t];
#pragma unroll 8
                for (int k = 0; k < F; k++) acc += sv[k] * W3[k * F + t];
                out[t] = acc;
                g_vec[t] = 0.f;
            }
            if (t == 0) g_done = 0;
        }
    }
}

extern "C" void kernel_launch(void* const* d_in, const int* in_sizes, int n_in,
                              void* d_out, int out_size) {
    const float* feat = (const float*)d_in[0];
    const float* W1   = (const float*)d_in[1];
    const float* b1   = (const float*)d_in[2];
    const float* W2   = (const float*)d_in[3];
    const float* b2   = (const float*)d_in[4];
    const float* W3   = (const float*)d_in[5];
    const float* b3   = (const float*)d_in[6];
    const int*   src  = (const int*)d_in[7];
    const int*   dst  = (const int*)d_in[8];
    float* out = (float*)d_out;

    cudaFuncSetAttribute(k_gemm<false>, cudaFuncAttributeMaxDynamicSharedMemorySize, SMEM_GEMM);
    cudaFuncSetAttribute(k_gemm<true>,  cudaFuncAttributeMaxDynamicSharedMemorySize, SMEM_GEMM);

    void *p0, *p1, *pm, *pw1, *pw2;
    cudaGetSymbolAddress(&p0, g_x0);
    cudaGetSymbolAddress(&p1, g_x1);
    cudaGetSymbolAddress(&pm, g_m);
    cudaGetSymbolAddress(&pw1, g_w1h);
    cudaGetSymbolAddress(&pw2, g_w2h);
    __half* x0 = (__half*)p0;
    __half* x1 = (__half*)p1;
    __half* mm = (__half*)pm;
    __half* w1h = (__half*)pw1;
    __half* w2h = (__half*)pw2;

    int nb_count = (N_EDGES / 4 + 255) / 256;        // 782
    int nb_aggw  = (N_NODES * 32 + 255) / 256;       // 6250
    int nb_gemm  = (N_NODES + GRM - 1) / GRM;        // 391
    int nb_fp    = (N_NODES * F / 4 + 255) / 256;    // 6250

    k_count<<<nb_count, 256>>>((const int4*)src, (const int4*)dst, W1, W2);
    k_scan1<<<NCH, CH>>>();
    k_scan23<<<NCH, CH>>>();
    k_fill_prep<<<nb_fp, 256>>>((const int4*)src, (const int4*)dst, feat);   // profiled (#4)
    k_agg<<<nb_aggw, 256>>>(x0, mm);
    k_gemm<false><<<nb_gemm, 256, SMEM_GEMM>>>(mm, w1h, b1, x1, W3, b3, out);
    k_agg<<<nb_aggw, 256>>>(x1, mm);
    k_gemm<true><<<nb_gemm, 256, SMEM_GEMM>>>(mm, w2h, b2, nullptr, W3, b3, out);
}

// round 13
// speedup vs baseline: 2.9364x; 1.1905x over previous
#include <cuda_runtime.h>
#include <cuda_fp16.h>
#include <mma.h>
#include <cstdint>

using namespace nvcuda;

#define N_NODES 50000
#define N_EDGES 800000
#define F 128
#define GRM 128                 // rows per GEMM block
#define LDA 136                 // padded leading dim (halves)
#define LDC 132                 // padded leading dim (floats) for C tile
#define CH 256
#define NCH ((N_NODES + CH - 1) / CH)   // 196
#define SMEM_GEMM (2 * GRM * LDA * 2)   // A + B tiles: 69632 B

// ---- scratch (no allocation allowed -> __device__ globals) ----
// deg arrays re-zeroed in k_fill; g_c reset by owning FOLD-gemm block;
// g_vec/g_done reset by FOLD-gemm's last block. Module zero-init covers run 1.
__device__ int    g_deg_src[N_NODES];
__device__ int    g_deg_dst[N_NODES];
__device__ float  g_out_norm[N_NODES];
__device__ float  g_in_norm[N_NODES];
__device__ int    g_row_ptr[N_NODES + 1];
__device__ int    g_cursor[N_NODES];
__device__ int    g_col_idx[N_EDGES];
__device__ int    g_chunk_sum[NCH];
__device__ float  g_c[N_NODES];        // c[s] = sum_{e: src=s} in_norm[dst_e]
__device__ __half g_x0[N_NODES * F];
__device__ __half g_x1[N_NODES * F];
__device__ __half g_m[N_NODES * F];
__device__ __half g_w1h[F * F];
__device__ __half g_w2h[F * F];
__device__ float  g_vec[F];
__device__ int    g_done;

// ---------------- setup ----------------
__global__ void k_count(const int4* __restrict__ src4, const int4* __restrict__ dst4,
                        const float* __restrict__ W1, const float* __restrict__ W2) {
    int i = blockIdx.x * blockDim.x + threadIdx.x;
    if (i < N_EDGES / 4) {
        int4 s = src4[i], d = dst4[i];
        atomicAdd(&g_deg_src[s.x], 1);
        atomicAdd(&g_deg_src[s.y], 1);
        atomicAdd(&g_deg_src[s.z], 1);
        atomicAdd(&g_deg_src[s.w], 1);
        atomicAdd(&g_deg_dst[d.x], 1);
        atomicAdd(&g_deg_dst[d.y], 1);
        atomicAdd(&g_deg_dst[d.z], 1);
        atomicAdd(&g_deg_dst[d.w], 1);
    }
    if (i < F * F) {
        g_w1h[i] = __float2half(W1[i]);
        g_w2h[i] = __float2half(W2[i]);
    }
}

__global__ void k_scan1() {
    __shared__ int s[CH];
    int t = threadIdx.x;
    int i = blockIdx.x * CH + t;
    int v = (i < N_NODES) ? g_deg_dst[i] : 0;
    s[t] = v;
    __syncthreads();
    for (int off = 1; off < CH; off <<= 1) {
        int x = 0;
        if (t >= off) x = s[t - off];
        __syncthreads();
        if (t >= off) s[t] += x;
        __syncthreads();
    }
    if (i < N_NODES) g_row_ptr[i + 1] = s[t];
    if (t == CH - 1) g_chunk_sum[blockIdx.x] = s[t];
}

__global__ void k_scan23() {
    __shared__ int s[CH];
    int t = threadIdx.x;
    int bid = blockIdx.x;
    int v = (t < NCH) ? g_chunk_sum[t] : 0;
    s[t] = v;
    __syncthreads();
    for (int off = 1; off < CH; off <<= 1) {
        int x = 0;
        if (t >= off) x = s[t - off];
        __syncthreads();
        if (t >= off) s[t] += x;
        __syncthreads();
    }
    int chunk_off = (bid > 0) ? s[bid - 1] : 0;
    int i = bid * CH + t;
    if (i < N_NODES) {
        int rp = g_row_ptr[i + 1] + chunk_off;
        g_row_ptr[i + 1] = rp;
        int d = g_deg_dst[i];
        g_cursor[i] = rp - d;
        g_in_norm[i]  = rsqrtf((float)max(d, 1));
        g_out_norm[i] = rsqrtf((float)max(g_deg_src[i], 1));
        if (i == 0) g_row_ptr[0] = 0;
    }
}

// CSR fill (int4) + c[s] accumulation + deg re-zero (runs on null stream)
__global__ void k_fill(const int4* __restrict__ src4, const int4* __restrict__ dst4) {
    int i = blockIdx.x * blockDim.x + threadIdx.x;
    if (i < N_NODES) { g_deg_src[i] = 0; g_deg_dst[i] = 0; }
    if (i < N_EDGES / 4) {
        int4 s = src4[i], d = dst4[i];
        float i0 = g_in_norm[d.x], i1 = g_in_norm[d.y];
        float i2 = g_in_norm[d.z], i3 = g_in_norm[d.w];
        int p;
        p = atomicAdd(&g_cursor[d.x], 1); g_col_idx[p] = s.x;
        p = atomicAdd(&g_cursor[d.y], 1); g_col_idx[p] = s.y;
        p = atomicAdd(&g_cursor[d.z], 1); g_col_idx[p] = s.z;
        p = atomicAdd(&g_cursor[d.w], 1); g_col_idx[p] = s.w;
        atomicAdd(&g_c[s.x], i0);
        atomicAdd(&g_c[s.y], i1);
        atomicAdd(&g_c[s.z], i2);
        atomicAdd(&g_c[s.w], i3);
    }
}

// feat -> fp16 prescaled (runs concurrently on stream 2)
__global__ void k_prep(const float* __restrict__ feat) {
    int i = blockIdx.x * blockDim.x + threadIdx.x;
    if (i < N_NODES * F / 4) {
        int base = i * 4;
        float on = g_out_norm[base >> 7];
        float4 v = *(const float4*)&feat[base];
        __half2 h01 = __floats2half2_rn(v.x * on, v.y * on);
        __half2 h23 = __floats2half2_rn(v.z * on, v.w * on);
        uint2 pk;
        pk.x = *(uint32_t*)&h01;
        pk.y = *(uint32_t*)&h23;
        *(uint2*)&g_x0[base] = pk;
    }
}

// ---------------- gather: warp per node, 2 edges/iter via 16-lane halves ----------------
// Each edge row = 256B = 16 uint4; lanes 0-15 handle even edge, 16-31 odd edge.
__global__ void __launch_bounds__(256)
k_agg(const __half* __restrict__ x, __half* __restrict__ m) {
    int w = (blockIdx.x * blockDim.x + threadIdx.x) >> 5;
    int lane = threadIdx.x & 31;
    if (w >= N_NODES) return;
    int half = lane >> 4, sl = lane & 15;
    const uint4* x4 = (const uint4*)x;
    const int* __restrict__ ci = g_col_idx;
    int beg = g_row_ptr[w], end = g_row_ptr[w + 1];
    float acc[8] = {0.f, 0.f, 0.f, 0.f, 0.f, 0.f, 0.f, 0.f};
    int e = beg;
    for (; e + 8 <= end; e += 8) {
        uint4 v0 = x4[ci[e + 0 + half] * 16 + sl];
        uint4 v1 = x4[ci[e + 2 + half] * 16 + sl];
        uint4 v2 = x4[ci[e + 4 + half] * 16 + sl];
        uint4 v3 = x4[ci[e + 6 + half] * 16 + sl];
        const __half2* h0 = (const __half2*)&v0;
        const __half2* h1 = (const __half2*)&v1;
        const __half2* h2 = (const __half2*)&v2;
        const __half2* h3 = (const __half2*)&v3;
#pragma unroll
        for (int k = 0; k < 4; k++) {
            __half2 s01 = __hadd2(h0[k], h1[k]);
            __half2 s23 = __hadd2(h2[k], h3[k]);
            __half2 s = __hadd2(s01, s23);
            float2 f = __half22float2(s);
            acc[2 * k]     += f.x;
            acc[2 * k + 1] += f.y;
        }
    }
    for (; e < end; e += 2) {
        int ee = e + half;
        if (ee < end) {
            uint4 v = x4[ci[ee] * 16 + sl];
            const __half2* h = (const __half2*)&v;
#pragma unroll
            for (int k = 0; k < 4; k++) {
                float2 f = __half22float2(h[k]);
                acc[2 * k]     += f.x;
                acc[2 * k + 1] += f.y;
            }
        }
    }
    // combine the two 16-lane halves
#pragma unroll
    for (int k = 0; k < 8; k++)
        acc[k] += __shfl_xor_sync(0xFFFFFFFFu, acc[k], 16);
    if (half == 0) {
        float sc = g_in_norm[w];
        __half2 h[4];
#pragma unroll
        for (int k = 0; k < 4; k++)
            h[k] = __floats2half2_rn(acc[2 * k] * sc, acc[2 * k + 1] * sc);
        ((uint4*)m)[w * 16 + sl] = *(uint4*)h;
    }
}

// ---------------- GEMM: m @ W + b -> relu -> *out_norm ----------------
// FOLD=false: write fp16 activations to y.
// FOLD=true:  stage C tile in smem, column-reduce with weights c[row]*out_norm,
//             accumulate g_vec; last block does out = g_vec @ W3 + b3.
template<bool FOLD>
__global__ void __launch_bounds__(256, 2)
k_gemm(const __half* __restrict__ m, const __half* __restrict__ wh,
       const float* __restrict__ b, __half* __restrict__ y,
       const float* __restrict__ W3, const float* __restrict__ b3,
       float* __restrict__ out) {
    extern __shared__ char smem[];
    __half* sA = (__half*)smem;                        // [128][LDA]
    __half* sB = (__half*)(smem + GRM * LDA * 2);      // [128][LDA]
    int t = threadIdx.x, warp = t >> 5, lane = t & 31;
    int row0 = blockIdx.x * GRM;

    {
        const uint4* asrc = (const uint4*)(m + (size_t)row0 * F);
        const uint4* bsrc = (const uint4*)wh;
        for (int i = t; i < GRM * 16; i += 256) {
            int r = i >> 4, c = i & 15;
            uint4 av = {0u, 0u, 0u, 0u};
            if (row0 + r < N_NODES) av = asrc[i];
            *(uint4*)&sA[r * LDA + c * 8] = av;
            *(uint4*)&sB[r * LDA + c * 8] = bsrc[i];
        }
    }
    __syncthreads();

    int wy = warp >> 1, wx = warp & 1;
    wmma::fragment<wmma::accumulator, 16, 16, 16, float> c[2][4];
#pragma unroll
    for (int i = 0; i < 2; i++)
#pragma unroll
        for (int j = 0; j < 4; j++) wmma::fill_fragment(c[i][j], 0.f);

#pragma unroll
    for (int k0 = 0; k0 < F; k0 += 16) {
        wmma::fragment<wmma::matrix_a, 16, 16, 16, __half, wmma::row_major> af[2];
        wmma::fragment<wmma::matrix_b, 16, 16, 16, __half, wmma::row_major> bf[4];
#pragma unroll
        for (int i = 0; i < 2; i++)
            wmma::load_matrix_sync(af[i], &sA[(wy * 32 + i * 16) * LDA + k0], LDA);
#pragma unroll
        for (int j = 0; j < 4; j++)
            wmma::load_matrix_sync(bf[j], &sB[k0 * LDA + wx * 64 + j * 16], LDA);
#pragma unroll
        for (int i = 0; i < 2; i++)
#pragma unroll
            for (int j = 0; j < 4; j++)
                wmma::mma_sync(c[i][j], af[i], bf[j], c[i][j]);
    }
    __syncthreads();   // sA/sB dead from here

    if (FOLD) {
        float* sC = (float*)smem;                      // [128][LDC] = 67584 B
        float* cw = (float*)smem + GRM * LDC;          // [128] row weights
        float* pr = cw + GRM;                          // [256] partials
#pragma unroll
        for (int i = 0; i < 2; i++)
#pragma unroll
            for (int j = 0; j < 4; j++)
                wmma::store_matrix_sync(&sC[(wy * 32 + i * 16) * LDC + wx * 64 + j * 16],
                                        c[i][j], LDC, wmma::mem_row_major);
        if (t < GRM) {
            int grow = row0 + t;
            if (grow < N_NODES) {
                cw[t] = g_c[grow] * g_out_norm[grow];
                g_c[grow] = 0.f;                        // reset for next replay
            } else {
                cw[t] = 0.f;
            }
        }
        __syncthreads();

        int col = t & 127, rh = t >> 7;
        float bb = b[col];
        float acc = 0.f;
#pragma unroll 8
        for (int r = rh * 64; r < rh * 64 + 64; r++)
            acc += fmaxf(sC[r * LDC + col] + bb, 0.f) * cw[r];
        pr[t] = acc;
        __syncthreads();
        if (t < F) atomicAdd(&g_vec[t], (pr[t] + pr[t + 128]) * (1.0f / N_NODES));
        __threadfence();
        __syncthreads();
        __shared__ int s_last;
        if (t == 0) s_last = (atomicAdd(&g_done, 1) == (int)gridDim.x - 1);
        __syncthreads();
        if (s_last) {
            __shared__ float sv[F];
            if (t < F) sv[t] = *((volatile float*)&g_vec[t]);
            __syncthreads();
            if (t < F) {
                float acc2 = b3[t];
#pragma unroll 8
                for (int k = 0; k < F; k++) acc2 += sv[k] * W3[k * F + t];
                out[t] = acc2;
                g_vec[t] = 0.f;
            }
            if (t == 0) g_done = 0;
        }
    } else {
        float* wscr = (float*)smem + warp * (16 * 20);
#pragma unroll
        for (int i = 0; i < 2; i++) {
#pragma unroll
            for (int j = 0; j < 4; j++) {
                wmma::store_matrix_sync(wscr, c[i][j], 20, wmma::mem_row_major);
                __syncwarp();
                if (lane < 16) {
                    int grow = row0 + wy * 32 + i * 16 + lane;
                    if (grow < N_NODES) {
                        float on = g_out_norm[grow];
                        const float* cr = &wscr[lane * 20];
                        __half2 hv[8];
#pragma unroll
                        for (int cc = 0; cc < 16; cc += 4) {
                            float4 bv = *(const float4*)&b[wx * 64 + j * 16 + cc];
                            float v0 = fmaxf(cr[cc]     + bv.x, 0.f) * on;
                            float v1 = fmaxf(cr[cc + 1] + bv.y, 0.f) * on;
                            float v2 = fmaxf(cr[cc + 2] + bv.z, 0.f) * on;
                            float v3 = fmaxf(cr[cc + 3] + bv.w, 0.f) * on;
                            hv[cc / 2]     = __floats2half2_rn(v0, v1);
                            hv[cc / 2 + 1] = __floats2half2_rn(v2, v3);
                        }
                        uint4* dstp = (uint4*)(y + (size_t)grow * F + wx * 64 + j * 16);
                        dstp[0] = *(uint4*)&hv[0];
                        dstp[1] = *(uint4*)&hv[4];
                    }
                }
                __syncwarp();
            }
        }
    }
}

extern "C" void kernel_launch(void* const* d_in, const int* in_sizes, int n_in,
                              void* d_out, int out_size) {
    const float* feat = (const float*)d_in[0];
    const float* W1   = (const float*)d_in[1];
    const float* b1   = (const float*)d_in[2];
    const float* W2   = (const float*)d_in[3];
    const float* b2   = (const float*)d_in[4];
    const float* W3   = (const float*)d_in[5];
    const float* b3   = (const float*)d_in[6];
    const int*   src  = (const int*)d_in[7];
    const int*   dst  = (const int*)d_in[8];
    float* out = (float*)d_out;

    cudaFuncSetAttribute(k_gemm<false>, cudaFuncAttributeMaxDynamicSharedMemorySize, SMEM_GEMM);
    cudaFuncSetAttribute(k_gemm<true>,  cudaFuncAttributeMaxDynamicSharedMemorySize, SMEM_GEMM);

    void *p0, *p1, *pm, *pw1, *pw2;
    cudaGetSymbolAddress(&p0, g_x0);
    cudaGetSymbolAddress(&p1, g_x1);
    cudaGetSymbolAddress(&pm, g_m);
    cudaGetSymbolAddress(&pw1, g_w1h);
    cudaGetSymbolAddress(&pw2, g_w2h);
    __half* x0 = (__half*)p0;
    __half* x1 = (__half*)p1;
    __half* mm = (__half*)pm;
    __half* w1h = (__half*)pw1;
    __half* w2h = (__half*)pw2;

    int nb_count = (N_EDGES / 4 + 255) / 256;        // 782
    int nb_aggw  = (N_NODES * 32 + 255) / 256;       // 6250
    int nb_gemm  = (N_NODES + GRM - 1) / GRM;        // 391
    int nb_prep  = (N_NODES * F / 4 + 255) / 256;    // 6250

    // fork-join: k_fill (null stream) || k_prep (s2), both after k_scan23
    cudaStream_t s2;
    cudaEvent_t ev_fork, ev_join;
    cudaStreamCreateWithFlags(&s2, cudaStreamNonBlocking);
    cudaEventCreateWithFlags(&ev_fork, cudaEventDisableTiming);
    cudaEventCreateWithFlags(&ev_join, cudaEventDisableTiming);

    k_count<<<nb_count, 256>>>((const int4*)src, (const int4*)dst, W1, W2);
    k_scan1<<<NCH, CH>>>();
    k_scan23<<<NCH, CH>>>();
    cudaEventRecord(ev_fork, 0);
    cudaStreamWaitEvent(s2, ev_fork, 0);
    k_fill<<<nb_count, 256>>>((const int4*)src, (const int4*)dst);   // null stream (#4 profiled)
    k_prep<<<nb_prep, 256, 0, s2>>>(feat);                           // concurrent
    cudaEventRecord(ev_join, s2);
    cudaStreamWaitEvent(0, ev_join, 0);

    k_agg<<<nb_aggw, 256>>>(x0, mm);
    k_gemm<false><<<nb_gemm, 256, SMEM_GEMM>>>(mm, w1h, b1, x1, W3, b3, out);
    k_agg<<<nb_aggw, 256>>>(x1, mm);
    k_gemm<true><<<nb_gemm, 256, SMEM_GEMM>>>(mm, w2h, b2, nullptr, W3, b3, out);

    cudaEventDestroy(ev_fork);
    cudaEventDestroy(ev_join);
    cudaStreamDestroy(s2);
}

// round 14
// speedup vs baseline: 2.9731x; 1.0125x over previous
#include <cuda_runtime.h>
#include <cuda_fp16.h>
#include <mma.h>
#include <cstdint>

using namespace nvcuda;

#define N_NODES 50000
#define N_EDGES 800000
#define F 128
#define GRM 128                 // rows per GEMM block
#define LDA 136                 // padded leading dim (halves)
#define LDC 132                 // padded leading dim (floats) for C tile
#define CH 256
#define NCH ((N_NODES + CH - 1) / CH)   // 196
#define SMEM_GEMM (2 * GRM * LDA * 2)   // A + B tiles: 69632 B

// ---- scratch (no allocation allowed -> __device__ globals) ----
// deg arrays re-zeroed in k_fill; g_c reset by owning FOLD-gemm block;
// g_vec/g_done reset by FOLD-gemm's last block. Module zero-init covers run 1.
__device__ int    g_deg_src[N_NODES];
__device__ int    g_deg_dst[N_NODES];
__device__ float  g_out_norm[N_NODES];
__device__ float  g_in_norm[N_NODES];
__device__ int    g_row_ptr[N_NODES + 1];
__device__ int    g_cursor[N_NODES];
__device__ int    g_col_idx[N_EDGES];
__device__ int    g_chunk_sum[NCH];
__device__ float  g_c[N_NODES];        // c[s] = sum_{e: src=s} in_norm[dst_e]
__device__ __half g_x0[N_NODES * F];
__device__ __half g_x1[N_NODES * F];
__device__ __half g_m[N_NODES * F];
__device__ __half g_w1h[F * F];
__device__ __half g_w2h[F * F];
__device__ float  g_vec[F];
__device__ int    g_done;

// ---------------- setup ----------------
// degrees: 1 edge/thread for max atomic MLP; W conversion folded in
__global__ void k_count(const int* __restrict__ src, const int* __restrict__ dst,
                        const float* __restrict__ W1, const float* __restrict__ W2) {
    int i = blockIdx.x * blockDim.x + threadIdx.x;
    if (i < N_EDGES) {
        atomicAdd(&g_deg_src[src[i]], 1);
        atomicAdd(&g_deg_dst[dst[i]], 1);
    }
    if (i < F * F) {
        g_w1h[i] = __float2half(W1[i]);
        g_w2h[i] = __float2half(W2[i]);
    }
}

__global__ void k_scan1() {
    __shared__ int s[CH];
    int t = threadIdx.x;
    int i = blockIdx.x * CH + t;
    int v = (i < N_NODES) ? g_deg_dst[i] : 0;
    s[t] = v;
    __syncthreads();
    for (int off = 1; off < CH; off <<= 1) {
        int x = 0;
        if (t >= off) x = s[t - off];
        __syncthreads();
        if (t >= off) s[t] += x;
        __syncthreads();
    }
    if (i < N_NODES) g_row_ptr[i + 1] = s[t];
    if (t == CH - 1) g_chunk_sum[blockIdx.x] = s[t];
}

__global__ void k_scan23() {
    __shared__ int s[CH];
    int t = threadIdx.x;
    int bid = blockIdx.x;
    int v = (t < NCH) ? g_chunk_sum[t] : 0;
    s[t] = v;
    __syncthreads();
    for (int off = 1; off < CH; off <<= 1) {
        int x = 0;
        if (t >= off) x = s[t - off];
        __syncthreads();
        if (t >= off) s[t] += x;
        __syncthreads();
    }
    int chunk_off = (bid > 0) ? s[bid - 1] : 0;
    int i = bid * CH + t;
    if (i < N_NODES) {
        int rp = g_row_ptr[i + 1] + chunk_off;
        g_row_ptr[i + 1] = rp;
        int d = g_deg_dst[i];
        g_cursor[i] = rp - d;
        g_in_norm[i]  = rsqrtf((float)max(d, 1));
        g_out_norm[i] = rsqrtf((float)max(g_deg_src[i], 1));
        if (i == 0) g_row_ptr[0] = 0;
    }
}

// CSR fill: 1 edge/thread (max atomic MLP) + c[s] + deg re-zero
__global__ void k_fill(const int* __restrict__ src, const int* __restrict__ dst) {
    int i = blockIdx.x * blockDim.x + threadIdx.x;
    if (i < N_NODES) { g_deg_src[i] = 0; g_deg_dst[i] = 0; }
    if (i < N_EDGES) {
        int s = src[i], d = dst[i];
        float in = g_in_norm[d];
        int p = atomicAdd(&g_cursor[d], 1);
        g_col_idx[p] = s;
        atomicAdd(&g_c[s], in);
    }
}

// feat -> fp16 prescaled (concurrent on stream 2)
__global__ void k_prep(const float* __restrict__ feat) {
    int i = blockIdx.x * blockDim.x + threadIdx.x;
    if (i < N_NODES * F / 4) {
        int base = i * 4;
        float on = g_out_norm[base >> 7];
        float4 v = *(const float4*)&feat[base];
        __half2 h01 = __floats2half2_rn(v.x * on, v.y * on);
        __half2 h23 = __floats2half2_rn(v.z * on, v.w * on);
        uint2 pk;
        pk.x = *(uint32_t*)&h01;
        pk.y = *(uint32_t*)&h23;
        *(uint2*)&g_x0[base] = pk;
    }
}

// ---------------- gather: warp per node, 2 edges/iter via 16-lane halves ----------------
__global__ void __launch_bounds__(256)
k_agg(const __half* __restrict__ x, __half* __restrict__ m) {
    int w = (blockIdx.x * blockDim.x + threadIdx.x) >> 5;
    int lane = threadIdx.x & 31;
    if (w >= N_NODES) return;
    int half = lane >> 4, sl = lane & 15;
    const uint4* x4 = (const uint4*)x;
    const int* __restrict__ ci = g_col_idx;
    int beg = g_row_ptr[w], end = g_row_ptr[w + 1];
    float acc[8] = {0.f, 0.f, 0.f, 0.f, 0.f, 0.f, 0.f, 0.f};
    int e = beg;
    for (; e + 8 <= end; e += 8) {
        uint4 v0 = x4[ci[e + 0 + half] * 16 + sl];
        uint4 v1 = x4[ci[e + 2 + half] * 16 + sl];
        uint4 v2 = x4[ci[e + 4 + half] * 16 + sl];
        uint4 v3 = x4[ci[e + 6 + half] * 16 + sl];
        const __half2* h0 = (const __half2*)&v0;
        const __half2* h1 = (const __half2*)&v1;
        const __half2* h2 = (const __half2*)&v2;
        const __half2* h3 = (const __half2*)&v3;
#pragma unroll
        for (int k = 0; k < 4; k++) {
            __half2 s01 = __hadd2(h0[k], h1[k]);
            __half2 s23 = __hadd2(h2[k], h3[k]);
            __half2 s = __hadd2(s01, s23);
            float2 f = __half22float2(s);
            acc[2 * k]     += f.x;
            acc[2 * k + 1] += f.y;
        }
    }
    for (; e < end; e += 2) {
        int ee = e + half;
        if (ee < end) {
            uint4 v = x4[ci[ee] * 16 + sl];
            const __half2* h = (const __half2*)&v;
#pragma unroll
            for (int k = 0; k < 4; k++) {
                float2 f = __half22float2(h[k]);
                acc[2 * k]     += f.x;
                acc[2 * k + 1] += f.y;
            }
        }
    }
#pragma unroll
    for (int k = 0; k < 8; k++)
        acc[k] += __shfl_xor_sync(0xFFFFFFFFu, acc[k], 16);
    if (half == 0) {
        float sc = g_in_norm[w];
        __half2 h[4];
#pragma unroll
        for (int k = 0; k < 4; k++)
            h[k] = __floats2half2_rn(acc[2 * k] * sc, acc[2 * k + 1] * sc);
        ((uint4*)m)[w * 16 + sl] = *(uint4*)h;
    }
}

// ---------------- GEMM: m @ W + b -> relu -> *out_norm ----------------
template<bool FOLD>
__global__ void __launch_bounds__(256, 2)
k_gemm(const __half* __restrict__ m, const __half* __restrict__ wh,
       const float* __restrict__ b, __half* __restrict__ y,
       const float* __restrict__ W3, const float* __restrict__ b3,
       float* __restrict__ out) {
    extern __shared__ char smem[];
    __half* sA = (__half*)smem;                        // [128][LDA]
    __half* sB = (__half*)(smem + GRM * LDA * 2);      // [128][LDA]
    int t = threadIdx.x, warp = t >> 5, lane = t & 31;
    int row0 = blockIdx.x * GRM;

    {
        const uint4* asrc = (const uint4*)(m + (size_t)row0 * F);
        const uint4* bsrc = (const uint4*)wh;
        for (int i = t; i < GRM * 16; i += 256) {
            int r = i >> 4, c = i & 15;
            uint4 av = {0u, 0u, 0u, 0u};
            if (row0 + r < N_NODES) av = asrc[i];
            *(uint4*)&sA[r * LDA + c * 8] = av;
            *(uint4*)&sB[r * LDA + c * 8] = bsrc[i];
        }
    }
    __syncthreads();

    int wy = warp >> 1, wx = warp & 1;
    wmma::fragment<wmma::accumulator, 16, 16, 16, float> c[2][4];
#pragma unroll
    for (int i = 0; i < 2; i++)
#pragma unroll
        for (int j = 0; j < 4; j++) wmma::fill_fragment(c[i][j], 0.f);

#pragma unroll
    for (int k0 = 0; k0 < F; k0 += 16) {
        wmma::fragment<wmma::matrix_a, 16, 16, 16, __half, wmma::row_major> af[2];
        wmma::fragment<wmma::matrix_b, 16, 16, 16, __half, wmma::row_major> bf[4];
#pragma unroll
        for (int i = 0; i < 2; i++)
            wmma::load_matrix_sync(af[i], &sA[(wy * 32 + i * 16) * LDA + k0], LDA);
#pragma unroll
        for (int j = 0; j < 4; j++)
            wmma::load_matrix_sync(bf[j], &sB[k0 * LDA + wx * 64 + j * 16], LDA);
#pragma unroll
        for (int i = 0; i < 2; i++)
#pragma unroll
            for (int j = 0; j < 4; j++)
                wmma::mma_sync(c[i][j], af[i], bf[j], c[i][j]);
    }
    __syncthreads();   // sA/sB dead from here

    if (FOLD) {
        float* sC = (float*)smem;                      // [128][LDC]
        float* cw = (float*)smem + GRM * LDC;          // [128] row weights
        float* pr = cw + GRM;                          // [256] partials
#pragma unroll
        for (int i = 0; i < 2; i++)
#pragma unroll
            for (int j = 0; j < 4; j++)
                wmma::store_matrix_sync(&sC[(wy * 32 + i * 16) * LDC + wx * 64 + j * 16],
                                        c[i][j], LDC, wmma::mem_row_major);
        if (t < GRM) {
            int grow = row0 + t;
            if (grow < N_NODES) {
                cw[t] = g_c[grow] * g_out_norm[grow];
                g_c[grow] = 0.f;
            } else {
                cw[t] = 0.f;
            }
        }
        __syncthreads();

        int col = t & 127, rh = t >> 7;
        float bb = b[col];
        float acc = 0.f;
#pragma unroll 8
        for (int r = rh * 64; r < rh * 64 + 64; r++)
            acc += fmaxf(sC[r * LDC + col] + bb, 0.f) * cw[r];
        pr[t] = acc;
        __syncthreads();
        if (t < F) atomicAdd(&g_vec[t], (pr[t] + pr[t + 128]) * (1.0f / N_NODES));
        __threadfence();
        __syncthreads();
        __shared__ int s_last;
        if (t == 0) s_last = (atomicAdd(&g_done, 1) == (int)gridDim.x - 1);
        __syncthreads();
        if (s_last) {
            __shared__ float sv[F];
            if (t < F) sv[t] = *((volatile float*)&g_vec[t]);
            __syncthreads();
            if (t < F) {
                float acc2 = b3[t];
#pragma unroll 8
                for (int k = 0; k < F; k++) acc2 += sv[k] * W3[k * F + t];
                out[t] = acc2;
                g_vec[t] = 0.f;
            }
            if (t == 0) g_done = 0;
        }
    } else {
        float* wscr = (float*)smem + warp * (16 * 20);
#pragma unroll
        for (int i = 0; i < 2; i++) {
#pragma unroll
            for (int j = 0; j < 4; j++) {
                wmma::store_matrix_sync(wscr, c[i][j], 20, wmma::mem_row_major);
                __syncwarp();
                if (lane < 16) {
                    int grow = row0 + wy * 32 + i * 16 + lane;
                    if (grow < N_NODES) {
                        float on = g_out_norm[grow];
                        const float* cr = &wscr[lane * 20];
                        __half2 hv[8];
#pragma unroll
                        for (int cc = 0; cc < 16; cc += 4) {
                            float4 bv = *(const float4*)&b[wx * 64 + j * 16 + cc];
                            float v0 = fmaxf(cr[cc]     + bv.x, 0.f) * on;
                            float v1 = fmaxf(cr[cc + 1] + bv.y, 0.f) * on;
                            float v2 = fmaxf(cr[cc + 2] + bv.z, 0.f) * on;
                            float v3 = fmaxf(cr[cc + 3] + bv.w, 0.f) * on;
                            hv[cc / 2]     = __floats2half2_rn(v0, v1);
                            hv[cc / 2 + 1] = __floats2half2_rn(v2, v3);
                        }
                        uint4* dstp = (uint4*)(y + (size_t)grow * F + wx * 64 + j * 16);
                        dstp[0] = *(uint4*)&hv[0];
                        dstp[1] = *(uint4*)&hv[4];
                    }
                }
                __syncwarp();
            }
        }
    }
}

extern "C" void kernel_launch(void* const* d_in, const int* in_sizes, int n_in,
                              void* d_out, int out_size) {
    const float* feat = (const float*)d_in[0];
    const float* W1   = (const float*)d_in[1];
    const float* b1   = (const float*)d_in[2];
    const float* W2   = (const float*)d_in[3];
    const float* b2   = (const float*)d_in[4];
    const float* W3   = (const float*)d_in[5];
    const float* b3   = (const float*)d_in[6];
    const int*   src  = (const int*)d_in[7];
    const int*   dst  = (const int*)d_in[8];
    float* out = (float*)d_out;

    cudaFuncSetAttribute(k_gemm<false>, cudaFuncAttributeMaxDynamicSharedMemorySize, SMEM_GEMM);
    cudaFuncSetAttribute(k_gemm<true>,  cudaFuncAttributeMaxDynamicSharedMemorySize, SMEM_GEMM);

    void *p0, *p1, *pm, *pw1, *pw2;
    cudaGetSymbolAddress(&p0, g_x0);
    cudaGetSymbolAddress(&p1, g_x1);
    cudaGetSymbolAddress(&pm, g_m);
    cudaGetSymbolAddress(&pw1, g_w1h);
    cudaGetSymbolAddress(&pw2, g_w2h);
    __half* x0 = (__half*)p0;
    __half* x1 = (__half*)p1;
    __half* mm = (__half*)pm;
    __half* w1h = (__half*)pw1;
    __half* w2h = (__half*)pw2;

    int nb_edge1 = (N_EDGES + 255) / 256;            // 3125 (1 edge/thread)
    int nb_aggw  = (N_NODES * 32 + 255) / 256;       // 6250
    int nb_gemm  = (N_NODES + GRM - 1) / GRM;        // 391
    int nb_prep  = (N_NODES * F / 4 + 255) / 256;    // 6250

    cudaStream_t s2;
    cudaEvent_t ev_fork, ev_join;
    cudaStreamCreateWithFlags(&s2, cudaStreamNonBlocking);
    cudaEventCreateWithFlags(&ev_fork, cudaEventDisableTiming);
    cudaEventCreateWithFlags(&ev_join, cudaEventDisableTiming);

    k_count<<<nb_edge1, 256>>>(src, dst, W1, W2);
    k_scan1<<<NCH, CH>>>();
    k_scan23<<<NCH, CH>>>();
    cudaEventRecord(ev_fork, 0);
    cudaStreamWaitEvent(s2, ev_fork, 0);
    k_fill<<<nb_edge1, 256>>>(src, dst);             // null stream (#4 profiled)
    k_prep<<<nb_prep, 256, 0, s2>>>(feat);           // concurrent
    cudaEventRecord(ev_join, s2);
    cudaStreamWaitEvent(0, ev_join, 0);

    k_agg<<<nb_aggw, 256>>>(x0, mm);
    k_gemm<false><<<nb_gemm, 256, SMEM_GEMM>>>(mm, w1h, b1, x1, W3, b3, out);
    k_agg<<<nb_aggw, 256>>>(x1, mm);
    k_gemm<true><<<nb_gemm, 256, SMEM_GEMM>>>(mm, w2h, b2, nullptr, W3, b3, out);

    cudaEventDestroy(ev_fork);
    cudaEventDestroy(ev_join);
    cudaStreamDestroy(s2);
}